// round 17
// baseline (speedup 1.0000x reference)
#include <cuda_runtime.h>
#include <cuda_bf16.h>
#include <cstdint>

#define CRF_S 512
#define CRF_B 256
#define CRF_L 128
#define PAD_ID 0
#define START_ID 1

typedef unsigned long long ull;

__device__ int g_mode;            // 0 = int32, 1 = byte, 2 = float32
__device__ int g_len[CRF_B];      // per-batch length
__device__ int g_sched[CRF_B];    // batch index sorted by length (ascending)

// ---------------------------------------------------------------------------
// Prep: detect mask dtype, compute all lengths, rank-sort batches, zero out.
// ---------------------------------------------------------------------------
__global__ void crf_prep(const void* __restrict__ masks, float* out) {
    __shared__ int flagByte, flagFloat;
    __shared__ int slen[CRF_B];
    int tid  = threadIdx.x;
    int wid  = tid >> 5;
    int lane = tid & 31;
    if (tid == 0) { flagByte = 0; flagFloat = 0; out[0] = 0.0f; }
    __syncthreads();

    const unsigned* mw = (const unsigned*)masks;
    int lb = 0, lf = 0;
    for (int k = tid; k < (CRF_B * CRF_S) / 4; k += 256) {
        unsigned w = mw[k];
        if (w == 0x3F800000u) lf = 1;          // float 1.0 pattern
        else if (w > 1u) lb = 1;               // byte-packed bools
    }
    if (lb) atomicOr(&flagByte, 1);
    if (lf) atomicOr(&flagFloat, 1);
    __syncthreads();
    int mode = flagFloat ? 2 : (flagByte ? 1 : 0);
    if (tid == 0) g_mode = mode;

    for (int b = wid; b < CRF_B; b += 8) {
        int cnt = 0;
        if (mode == 1) {
            const unsigned char* mb = (const unsigned char*)masks + (size_t)b * CRF_S;
            for (int k = lane; k < CRF_S; k += 32) cnt += (mb[k] != 0);
        } else if (mode == 2) {
            const float* mf = (const float*)masks + (size_t)b * CRF_S;
            for (int k = lane; k < CRF_S; k += 32) cnt += (mf[k] != 0.0f);
        } else {
            const int* mi = (const int*)masks + (size_t)b * CRF_S;
            for (int k = lane; k < CRF_S; k += 32) cnt += (mi[k] != 0);
        }
        #pragma unroll
        for (int o = 16; o; o >>= 1) cnt += __shfl_xor_sync(0xffffffffu, cnt, o);
        if (cnt < 1) cnt = 1;
        if (lane == 0) { slen[b] = cnt; g_len[b] = cnt; }
    }
    __syncthreads();

    int mylen = slen[tid];
    int rank = 0;
    for (int j = 0; j < CRF_B; j++) {
        int lj = slen[j];
        rank += (lj < mylen) || (lj == mylen && j < tid);
    }
    g_sched[rank] = tid;
}

// ---- helpers ----
__device__ __forceinline__ unsigned packbf2(float lo, float hi) {
    unsigned r;
    asm("cvt.rn.bf16x2.f32 %0, %1, %2;" : "=r"(r) : "f"(hi), "f"(lo));
    return r;
}
__device__ __forceinline__ float bf_lo(unsigned v) { return __uint_as_float(v << 16); }
__device__ __forceinline__ float rcpf(float x) {
    float r; asm("rcp.approx.f32 %0, %1;" : "=f"(r) : "f"(x)); return r;
}

// m16n8k16 bf16 MMA, f32 accumulate in place (D == C)
#define MMA16816(d, a, b0, b1)                                                 \
    asm volatile(                                                              \
        "mma.sync.aligned.m16n8k16.row.col.f32.bf16.bf16.f32 "                 \
        "{%0,%1,%2,%3}, {%4,%5,%6,%7}, {%8,%9}, {%0,%1,%2,%3};"                \
        : "+f"((d)[0]), "+f"((d)[1]), "+f"((d)[2]), "+f"((d)[3])               \
        : "r"((a)[0]), "r"((a)[1]), "r"((a)[2]), "r"((a)[3]),                  \
          "r"(b0), "r"(b1))

// group barrier: 128 threads, named barrier id = group+1
#define GBAR(id) asm volatile("bar.sync %0, 128;" :: "r"(id) : "memory")

// ---------------------------------------------------------------------------
// Main: 128 blocks x 256 threads; two independent 128-thread groups per block,
// LENGTH-SORT PAIRED (block k hosts g_sched[k] and g_sched[255-k]) so the
// critical (longest) batch runs nearly solo on its SM.
//
// Matvec dot_j = sum_i p[i] * expT[i][j] runs on the tensor pipe via classic
// mma.sync m16n8k16 (bf16 in, f32 acc). Warp w owns output rows 32w..32w+31
// (2 M-tiles); A = expT^T fragments stationary in 64 regs; B = p broadcast
// from smem. p-buffer is CLASS-PERMUTED (word w stored at (w&7)*8 + (w>>3))
// so each lane's 16 B-words are 4 contiguous LDS.128. 4 accumulators give
// depth-4 HMMA chains. Column-0 results (c=0 lanes, d0/d2) are redistributed
// to owner threads with 4 shfl.idx + select.
//
// Exp/log-free recurrence (self-consistent): p_t[j] = dot_j * exp(e_t[j]) *
// rcp(p_{t-1}[0]); M += log(p_{t-1}[0]) off-chain.
// Final: encode_b = M + log( sum_j p[j] * exp(T[j][PAD]) ).
// ---------------------------------------------------------------------------
__global__ void __launch_bounds__(256, 1) crf_main(
    const float* __restrict__ emit,
    const int*   __restrict__ labels,
    const float* __restrict__ T,
    float* out)
{
    __shared__ __align__(16) __nv_bfloat16 sm_p[2][CRF_L];   // [group][perm word space]
    __shared__ __align__(16) float sm_red[2][4];
    __shared__ __align__(16) float sm_m0[2];

    int tid  = threadIdx.x;
    int grp  = tid >> 7;            // 0 short-side, 1 long-side
    int gt   = tid & 127;           // thread-in-group == state j
    int lane = tid & 31;
    int wgrp = gt >> 5;             // warp within group (0..3)
    int barid = grp + 1;

    int b   = grp ? g_sched[255 - blockIdx.x] : g_sched[blockIdx.x];
    int len = g_len[b];

    // ---- A fragments: expT^T, warp wgrp rows jb..jb+31, 2 tiles x 8 chunks ----
    // a0 = A[g][2c],A[g][2c+1]; a1 = rows g+8; a2 = cols +8; a3 = both.
    // A[r][k] = exp(T[16kc+k][jb16 + r]).
    int g = lane >> 2;
    int c = lane & 3;
    unsigned af[2][8][4];
    {
        int jb = 32 * wgrp;
        #pragma unroll
        for (int tile = 0; tile < 2; tile++) {
            int r0 = jb + 16 * tile + g;
            int r1 = r0 + 8;
            #pragma unroll
            for (int kc = 0; kc < 8; kc++) {
                int k0 = 16 * kc + 2 * c;
                af[tile][kc][0] = packbf2(__expf(T[(k0)     * CRF_L + r0]),
                                          __expf(T[(k0 + 1) * CRF_L + r0]));
                af[tile][kc][1] = packbf2(__expf(T[(k0)     * CRF_L + r1]),
                                          __expf(T[(k0 + 1) * CRF_L + r1]));
                af[tile][kc][2] = packbf2(__expf(T[(k0 + 8) * CRF_L + r0]),
                                          __expf(T[(k0 + 9) * CRF_L + r0]));
                af[tile][kc][3] = packbf2(__expf(T[(k0 + 8) * CRF_L + r1]),
                                          __expf(T[(k0 + 9) * CRF_L + r1]));
            }
        }
    }

    // ---- gold path (warp 0 of each group) ----
    float gold = 0.f, ends = 0.f;
    if (wgrp == 0) {
        for (int t = lane; t < len; t += 32) {
            int lab  = labels[b * CRF_S + t];
            int prev = (t == 0) ? START_ID : labels[b * CRF_S + t - 1];
            gold += emit[((size_t)t * CRF_B + b) * CRF_L + lab] + T[prev * CRF_L + lab];
        }
        #pragma unroll
        for (int o = 16; o; o >>= 1) gold += __shfl_xor_sync(0xffffffffu, gold, o);
        ends = T[labels[b * CRF_S + (len - 1)] * CRF_L + PAD_ID];
    }

    // ---- init: fs0_j = emit[0][b][j] + T[START][j]; M = fs0[0]; p0 = exp(fs0-M) ----
    float fs0 = emit[(size_t)b * CRF_L + gt] + T[START_ID * CRF_L + gt];
    if (gt == 0) sm_m0[grp] = fs0;
    GBAR(barid);
    float M = sm_m0[grp];
    float p = __expf(fs0 - M);

    // class-permuted p slot for state j: word w=j>>1 stored at (w&7)*8 + (w>>3)
    {
        int w = gt >> 1;
        int nw = (w & 7) * 8 + (w >> 3);
    }
    __nv_bfloat16* pbuf = sm_p[grp];
    int wstd = gt >> 1;
    __nv_bfloat16* bslot = pbuf + ((wstd & 7) * 8 + (wstd >> 3)) * 2 + (gt & 1);
    const uint4* pb4 = reinterpret_cast<const uint4*>(pbuf);

    // redistribution constants for this thread's j = gt
    int rr   = gt & 15;
    int srcLane = (rr & 7) * 4;
    bool hi8  = rr >= 8;
    bool tl1  = (gt & 31) >= 16;

    // ---- emit prefetch pipeline (depth 2) ----
    const long estride = (long)CRF_B * CRF_L;
    const float* ep = emit + estride + (size_t)b * CRF_L + gt;   // t=1
    float e_cur = 0.f, e_n = 0.f;
    if (len > 1) e_cur = ep[0];
    if (len > 2) e_n   = ep[estride];

    // ---- forward scan ----
    for (int t = 1; t < len; t++) {
        *bslot = __float2bfloat16(p);             // publish p_{t-1}[j] (permuted)
        GBAR(barid);

        // B words: class c (b0 for kc=0..7) and class c+4 (b1)
        uint4 B0a = pb4[2 * c];
        uint4 B0b = pb4[2 * c + 1];
        uint4 B1a = pb4[2 * (c + 4)];
        uint4 B1b = pb4[2 * (c + 4) + 1];

        // off-chain scalars (word 0 of class 0 = std word 0 -> p_prev[0])
        float p0prev = __bfloat162float(pbuf[0]);
        float r = rcpf(p0prev);
        M += __logf(p0prev);
        float expE = __expf(e_cur);
        float e_f = 0.f;
        if (t + 2 < len) e_f = ep[2 * estride];

        // 16 HMMA, 4 accumulators (depth-4 chains)
        float acc[4][4];
        #pragma unroll
        for (int q = 0; q < 4; q++)
            #pragma unroll
            for (int e = 0; e < 4; e++) acc[q][e] = 0.f;

        unsigned W0[8] = {B0a.x, B0a.y, B0a.z, B0a.w, B0b.x, B0b.y, B0b.z, B0b.w};
        unsigned W1[8] = {B1a.x, B1a.y, B1a.z, B1a.w, B1b.x, B1b.y, B1b.z, B1b.w};

        #pragma unroll
        for (int kc = 0; kc < 4; kc++) {
            MMA16816(acc[0], af[0][kc],     W0[kc],     W1[kc]);
            MMA16816(acc[2], af[1][kc],     W0[kc],     W1[kc]);
            MMA16816(acc[1], af[0][kc + 4], W0[kc + 4], W1[kc + 4]);
            MMA16816(acc[3], af[1][kc + 4], W0[kc + 4], W1[kc + 4]);
        }

        // combine split-K; only col-0 regs (d0, d2) matter
        float t0d0 = acc[0][0] + acc[1][0];
        float t0d2 = acc[0][2] + acc[1][2];
        float t1d0 = acc[2][0] + acc[3][0];
        float t1d2 = acc[2][2] + acc[3][2];

        // redistribute to owner thread (results live in c==0 lanes)
        float v00 = __shfl_sync(0xffffffffu, t0d0, srcLane);
        float v02 = __shfl_sync(0xffffffffu, t0d2, srcLane);
        float v10 = __shfl_sync(0xffffffffu, t1d0, srcLane);
        float v12 = __shfl_sync(0xffffffffu, t1d2, srcLane);
        float dot = tl1 ? (hi8 ? v12 : v10) : (hi8 ? v02 : v00);

        p = dot * (expE * r);                     // exp/log-free p update

        e_cur = e_n; e_n = e_f;
        ep += estride;
    }

    // ---- encode_b = M + log( sum_j p[j] * exp(T[j][PAD]) ) ----
    float y = p * __expf(T[gt * CRF_L + PAD_ID]);
    #pragma unroll
    for (int o = 16; o; o >>= 1) y += __shfl_xor_sync(0xffffffffu, y, o);
    if (lane == 0) sm_red[grp][wgrp] = y;
    GBAR(barid);
    if (gt == 0) {
        float4 sv = *reinterpret_cast<float4*>(sm_red[grp]);
        float r2 = M + __logf(sv.x + sv.y + sv.z + sv.w);
        atomicAdd(out, r2 - gold - ends);
    }
}

// ---------------------------------------------------------------------------
extern "C" void kernel_launch(void* const* d_in, const int* in_sizes, int n_in,
                              void* d_out, int out_size) {
    const float* emit   = (const float*)d_in[0];
    const int*   labels = (const int*)d_in[1];
    const void*  masks  = d_in[2];
    const float* T      = (const float*)d_in[3];
    float* out = (float*)d_out;

    (void)in_sizes; (void)n_in; (void)out_size;

    crf_prep<<<1, 256>>>(masks, out);
    crf_main<<<CRF_B / 2, 256>>>(emit, labels, T, out);
}